// round 11
// baseline (speedup 1.0000x reference)
#include <cuda_runtime.h>

#define OUT_DIM 512
#define NUM_S   4096
#define NUM_A   128
#define ELEMS_PER_O (NUM_S * NUM_A)       // 524288 floats per output row
#define V4_PER_O    (ELEMS_PER_O / 4)     // 131072 float4 per output row
#define SPLIT       4
#define V4_PER_BLK  (V4_PER_O / SPLIT)    // 32768 float4 per CTA
#define THREADS     512

__global__ void lsh_zero_kernel(float* __restrict__ out) {
    int i = blockIdx.x * blockDim.x + threadIdx.x;
    if (i < OUT_DIM) out[i] = 0.0f;
}

__global__ __launch_bounds__(THREADS)
void lsh_reduce_kernel(const float* __restrict__ x,
                       const float* __restrict__ w,
                       float* __restrict__ out) {
    const int o     = blockIdx.x;   // output index [0, 512)
    const int split = blockIdx.y;   // K-split [0, SPLIT)

    const float4* __restrict__ w4 =
        reinterpret_cast<const float4*>(w)
        + (size_t)o * V4_PER_O
        + (size_t)split * V4_PER_BLK;

    const int v4_base = split * V4_PER_BLK;  // global float4 offset within this o

    // Two independent accumulator chains; 2-way interleaved stride loop.
    // V4_PER_BLK / (2*THREADS) = 32 iterations, exact.
    float acc0 = 0.0f, acc1 = 0.0f;
    #pragma unroll 2
    for (int i = threadIdx.x; i < V4_PER_BLK; i += 2 * THREADS) {
        const int j = i + THREADS;
        float4 v0 = __ldlu(&w4[i]);
        float4 v1 = __ldlu(&w4[j]);
        float x0 = __ldg(&x[(v4_base + i) >> 5]);  // 32 float4 per s-row
        float x1 = __ldg(&x[(v4_base + j) >> 5]);
        acc0 += x0 * ((v0.x + v0.y) + (v0.z + v0.w));
        acc1 += x1 * ((v1.x + v1.y) + (v1.z + v1.w));
    }
    float acc = acc0 + acc1;

    // warp reduce
    #pragma unroll
    for (int off = 16; off > 0; off >>= 1)
        acc += __shfl_down_sync(0xffffffffu, acc, off);

    __shared__ float sm[THREADS / 32];
    if ((threadIdx.x & 31) == 0) sm[threadIdx.x >> 5] = acc;
    __syncthreads();

    if (threadIdx.x < (THREADS / 32)) {
        float v = sm[threadIdx.x];
        #pragma unroll
        for (int off = (THREADS / 64); off > 0; off >>= 1)
            v += __shfl_down_sync(0xffffu, v, off);
        if (threadIdx.x == 0) atomicAdd(&out[o], v);
    }
}

extern "C" void kernel_launch(void* const* d_in, const int* in_sizes, int n_in,
                              void* d_out, int out_size) {
    const float* x = (const float*)d_in[0];  // [1, 4096]
    const float* w = (const float*)d_in[1];  // [512, 4096, 128]
    float* out = (float*)d_out;              // [512]

    lsh_zero_kernel<<<(OUT_DIM + 255) / 256, 256>>>(out);

    dim3 grid(OUT_DIM, SPLIT);
    lsh_reduce_kernel<<<grid, THREADS>>>(x, w, out);
}

// round 12
// speedup vs baseline: 1.0035x; 1.0035x over previous
#include <cuda_runtime.h>

#define OUT_DIM 512
#define NUM_S   4096
#define NUM_A   128
#define ELEMS_PER_O (NUM_S * NUM_A)       // 524288 floats per output row
#define V4_PER_O    (ELEMS_PER_O / 4)     // 131072 float4 per output row
#define SPLIT       4
#define V4_PER_BLK  (V4_PER_O / SPLIT)    // 32768 float4 per CTA
#define THREADS     256

__global__ void lsh_zero_kernel(float* __restrict__ out) {
    int i = blockIdx.x * blockDim.x + threadIdx.x;
    if (i < OUT_DIM) out[i] = 0.0f;
}

__global__ __launch_bounds__(THREADS)
void lsh_reduce_kernel(const float* __restrict__ x,
                       const float* __restrict__ w,
                       float* __restrict__ out) {
    const int o     = blockIdx.x;   // output index [0, 512)
    const int split = blockIdx.y;   // K-split [0, SPLIT)

    const float4* __restrict__ w4 =
        reinterpret_cast<const float4*>(w)
        + (size_t)o * V4_PER_O
        + (size_t)split * V4_PER_BLK;

    const int v4_base = split * V4_PER_BLK;  // global float4 offset within this o

    // Two independent accumulator chains; 2-way interleaved stride loop.
    // Weights are read exactly once -> last-use hint (evict after read).
    // V4_PER_BLK / (2*THREADS) = 64 iterations, exact.
    float acc0 = 0.0f, acc1 = 0.0f;
    #pragma unroll 2
    for (int i = threadIdx.x; i < V4_PER_BLK; i += 2 * THREADS) {
        const int j = i + THREADS;
        float4 v0 = __ldlu(&w4[i]);
        float4 v1 = __ldlu(&w4[j]);
        float x0 = __ldg(&x[(v4_base + i) >> 5]);  // 32 float4 per s-row
        float x1 = __ldg(&x[(v4_base + j) >> 5]);
        acc0 += x0 * ((v0.x + v0.y) + (v0.z + v0.w));
        acc1 += x1 * ((v1.x + v1.y) + (v1.z + v1.w));
    }
    float acc = acc0 + acc1;

    // warp reduce
    #pragma unroll
    for (int off = 16; off > 0; off >>= 1)
        acc += __shfl_down_sync(0xffffffffu, acc, off);

    __shared__ float sm[THREADS / 32];
    if ((threadIdx.x & 31) == 0) sm[threadIdx.x >> 5] = acc;
    __syncthreads();

    if (threadIdx.x < (THREADS / 32)) {
        float v = sm[threadIdx.x];
        #pragma unroll
        for (int off = (THREADS / 64); off > 0; off >>= 1)
            v += __shfl_down_sync(0xffu, v, off);
        if (threadIdx.x == 0) atomicAdd(&out[o], v);
    }
}

extern "C" void kernel_launch(void* const* d_in, const int* in_sizes, int n_in,
                              void* d_out, int out_size) {
    const float* x = (const float*)d_in[0];  // [1, 4096]
    const float* w = (const float*)d_in[1];  // [512, 4096, 128]
    float* out = (float*)d_out;              // [512]

    lsh_zero_kernel<<<(OUT_DIM + 255) / 256, 256>>>(out);

    dim3 grid(OUT_DIM, SPLIT);
    lsh_reduce_kernel<<<grid, THREADS>>>(x, w, out);
}

// round 13
// speedup vs baseline: 1.0038x; 1.0002x over previous
#include <cuda_runtime.h>

#define OUT_DIM 512
#define NUM_S   4096
#define NUM_A   128
#define ELEMS_PER_O (NUM_S * NUM_A)       // 524288 floats per output row
#define V4_PER_O    (ELEMS_PER_O / 4)     // 131072 float4 per output row
#define SPLIT       4
#define V4_PER_BLK  (V4_PER_O / SPLIT)    // 32768 float4 per CTA
#define THREADS     256

__global__ __launch_bounds__(THREADS)
void lsh_reduce_kernel(const float* __restrict__ x,
                       const float* __restrict__ w,
                       float* __restrict__ out) {
    const int o     = blockIdx.x;   // output index [0, 512)
    const int split = blockIdx.y;   // K-split [0, SPLIT)

    const float4* __restrict__ w4 =
        reinterpret_cast<const float4*>(w)
        + (size_t)o * V4_PER_O
        + (size_t)split * V4_PER_BLK;

    const int v4_base = split * V4_PER_BLK;  // global float4 offset within this o

    // Two independent accumulator chains; 2-way interleaved stride loop.
    // Weights are read exactly once -> last-use hint (evict after read).
    // V4_PER_BLK / (2*THREADS) = 64 iterations, exact.
    float acc0 = 0.0f, acc1 = 0.0f;
    #pragma unroll 2
    for (int i = threadIdx.x; i < V4_PER_BLK; i += 2 * THREADS) {
        const int j = i + THREADS;
        float4 v0 = __ldlu(&w4[i]);
        float4 v1 = __ldlu(&w4[j]);
        float x0 = __ldg(&x[(v4_base + i) >> 5]);  // 32 float4 per s-row
        float x1 = __ldg(&x[(v4_base + j) >> 5]);
        acc0 += x0 * ((v0.x + v0.y) + (v0.z + v0.w));
        acc1 += x1 * ((v1.x + v1.y) + (v1.z + v1.w));
    }
    float acc = acc0 + acc1;

    // warp reduce
    #pragma unroll
    for (int off = 16; off > 0; off >>= 1)
        acc += __shfl_down_sync(0xffffffffu, acc, off);

    __shared__ float sm[THREADS / 32];
    if ((threadIdx.x & 31) == 0) sm[threadIdx.x >> 5] = acc;
    __syncthreads();

    if (threadIdx.x < (THREADS / 32)) {
        float v = sm[threadIdx.x];
        #pragma unroll
        for (int off = (THREADS / 64); off > 0; off >>= 1)
            v += __shfl_down_sync(0xffu, v, off);
        if (threadIdx.x == 0) atomicAdd(&out[o], v);
    }
}

extern "C" void kernel_launch(void* const* d_in, const int* in_sizes, int n_in,
                              void* d_out, int out_size) {
    const float* x = (const float*)d_in[0];  // [1, 4096]
    const float* w = (const float*)d_in[1];  // [512, 4096, 128]
    float* out = (float*)d_out;              // [512]

    // Zero the output via a memset node (graph-capturable, cheaper than a
    // kernel node). out is poisoned to 0xAA by the harness before timing.
    cudaMemsetAsync(out, 0, OUT_DIM * sizeof(float));

    dim3 grid(OUT_DIM, SPLIT);
    lsh_reduce_kernel<<<grid, THREADS>>>(x, w, out);
}

// round 14
// speedup vs baseline: 1.0162x; 1.0124x over previous
#include <cuda_runtime.h>

#define OUT_DIM 512
#define NUM_S   4096
#define NUM_A   128
#define ELEMS_PER_O (NUM_S * NUM_A)       // 524288 floats per output row
#define V4_PER_O    (ELEMS_PER_O / 4)     // 131072 float4 per output row
#define SPLIT       4
#define V4_PER_BLK  (V4_PER_O / SPLIT)    // 32768 float4 per CTA
#define THREADS     256

__global__ void lsh_zero_kernel(float* __restrict__ out) {
    int i = blockIdx.x * blockDim.x + threadIdx.x;
    if (i < OUT_DIM) out[i] = 0.0f;
}

__global__ __launch_bounds__(THREADS)
void lsh_reduce_kernel(const float* __restrict__ x,
                       const float* __restrict__ w,
                       float* __restrict__ out) {
    const int o     = blockIdx.x;   // output index [0, 512)
    const int split = blockIdx.y;   // K-split [0, SPLIT)

    const float4* __restrict__ w4 =
        reinterpret_cast<const float4*>(w)
        + (size_t)o * V4_PER_O
        + (size_t)split * V4_PER_BLK;

    const int v4_base = split * V4_PER_BLK;  // global float4 offset within this o

    // Two independent accumulator chains; 2-way interleaved stride loop.
    // V4_PER_BLK / (2*THREADS) = 64 iterations, exact.
    float acc0 = 0.0f, acc1 = 0.0f;
    #pragma unroll 2
    for (int i = threadIdx.x; i < V4_PER_BLK; i += 2 * THREADS) {
        const int j = i + THREADS;
        float4 v0 = w4[i];
        float4 v1 = w4[j];
        float x0 = __ldg(&x[(v4_base + i) >> 5]);  // 32 float4 per s-row
        float x1 = __ldg(&x[(v4_base + j) >> 5]);
        acc0 += x0 * ((v0.x + v0.y) + (v0.z + v0.w));
        acc1 += x1 * ((v1.x + v1.y) + (v1.z + v1.w));
    }
    float acc = acc0 + acc1;

    // warp reduce
    #pragma unroll
    for (int off = 16; off > 0; off >>= 1)
        acc += __shfl_down_sync(0xffffffffu, acc, off);

    __shared__ float sm[THREADS / 32];
    if ((threadIdx.x & 31) == 0) sm[threadIdx.x >> 5] = acc;
    __syncthreads();

    if (threadIdx.x < (THREADS / 32)) {
        float v = sm[threadIdx.x];
        #pragma unroll
        for (int off = (THREADS / 64); off > 0; off >>= 1)
            v += __shfl_down_sync(0xffu, v, off);
        if (threadIdx.x == 0) atomicAdd(&out[o], v);
    }
}

extern "C" void kernel_launch(void* const* d_in, const int* in_sizes, int n_in,
                              void* d_out, int out_size) {
    const float* x = (const float*)d_in[0];  // [1, 4096]
    const float* w = (const float*)d_in[1];  // [512, 4096, 128]
    float* out = (float*)d_out;              // [512]

    lsh_zero_kernel<<<(OUT_DIM + 255) / 256, 256>>>(out);

    dim3 grid(OUT_DIM, SPLIT);
    lsh_reduce_kernel<<<grid, THREADS>>>(x, w, out);
}